// round 1
// baseline (speedup 1.0000x reference)
#include <cuda_runtime.h>
#include <cstdint>

// ---------------------------------------------------------------------------
// GroupEmbedding:
//   per_user_beh[u,:] = sum_{j in seg(u)} item_table[bitem[j],:] * bcnt[j]
//   per_user[u,:]     = per_user_beh[u,:] * user_table[user_ids[u],:] * (user_ids[u]!=0)
//   out[g,:]          = sum_{u in grpseg(g)} per_user[u,:]
// behavior_user_ids and user_group_ids are SORTED -> binary-search segments,
// fully deterministic reductions (no atomics).
// ---------------------------------------------------------------------------

#define EMB 128
#define MAX_USERS 65536

// 65536 users x 128 f32 = 32 MB scratch (allocation-free rule: __device__ global)
__device__ float g_per_user[(size_t)MAX_USERS * EMB];

__device__ __forceinline__ int lower_bound_i32(const int* __restrict__ a, int n, int key) {
    int lo = 0, hi = n;
    while (lo < hi) {
        int m = (lo + hi) >> 1;
        if (a[m] < key) lo = m + 1; else hi = m;
    }
    return lo;
}

// Kernel 1: one warp per user.
__global__ void __launch_bounds__(256) per_user_kernel(
    const int* __restrict__ user_ids,
    const int* __restrict__ bitem,
    const float* __restrict__ bcnt,
    const int* __restrict__ buid,
    const float* __restrict__ user_table,
    const float* __restrict__ item_table,
    int n_users, int n_beh)
{
    int warp = (blockIdx.x * blockDim.x + threadIdx.x) >> 5;
    int lane = threadIdx.x & 31;
    if (warp >= n_users) return;
    const int u = warp;

    // segment [s, e) of behaviors belonging to user u (buid is sorted)
    int s = lower_bound_i32(buid, n_beh, u);
    int e = lower_bound_i32(buid, n_beh, u + 1);

    float4 acc = make_float4(0.f, 0.f, 0.f, 0.f);
    const int col = lane * 4;

    int j = s;
    // unroll x2 for memory-level parallelism on the gather
    for (; j + 1 < e; j += 2) {
        int   it0 = bitem[j];
        int   it1 = bitem[j + 1];
        float c0  = bcnt[j];
        float c1  = bcnt[j + 1];
        float4 v0 = *reinterpret_cast<const float4*>(item_table + (size_t)it0 * EMB + col);
        float4 v1 = *reinterpret_cast<const float4*>(item_table + (size_t)it1 * EMB + col);
        acc.x += c0 * v0.x; acc.y += c0 * v0.y; acc.z += c0 * v0.z; acc.w += c0 * v0.w;
        acc.x += c1 * v1.x; acc.y += c1 * v1.y; acc.z += c1 * v1.z; acc.w += c1 * v1.w;
    }
    if (j < e) {
        int   it0 = bitem[j];
        float c0  = bcnt[j];
        float4 v0 = *reinterpret_cast<const float4*>(item_table + (size_t)it0 * EMB + col);
        acc.x += c0 * v0.x; acc.y += c0 * v0.y; acc.z += c0 * v0.z; acc.w += c0 * v0.w;
    }

    // user embedding with padding_idx = 0
    int uid = user_ids[u];
    float4 ue = make_float4(0.f, 0.f, 0.f, 0.f);
    if (uid != 0) {
        ue = *reinterpret_cast<const float4*>(user_table + (size_t)uid * EMB + col);
    }

    float4 outv;
    outv.x = acc.x * ue.x;
    outv.y = acc.y * ue.y;
    outv.z = acc.z * ue.z;
    outv.w = acc.w * ue.w;

    *reinterpret_cast<float4*>(g_per_user + (size_t)u * EMB + col) = outv;
}

// Kernel 2: one 128-thread CTA per group; thread t owns embedding column t.
__global__ void __launch_bounds__(EMB) group_sum_kernel(
    const int* __restrict__ ugid,
    float* __restrict__ out,
    int n_users, int num_groups)
{
    int g = blockIdx.x;
    int t = threadIdx.x;
    if (g >= num_groups) return;

    int s = lower_bound_i32(ugid, n_users, g);
    int e = lower_bound_i32(ugid, n_users, g + 1);

    float acc = 0.f;
    int u = s;
    for (; u + 3 < e; u += 4) {
        float a0 = g_per_user[(size_t)(u + 0) * EMB + t];
        float a1 = g_per_user[(size_t)(u + 1) * EMB + t];
        float a2 = g_per_user[(size_t)(u + 2) * EMB + t];
        float a3 = g_per_user[(size_t)(u + 3) * EMB + t];
        acc += a0; acc += a1; acc += a2; acc += a3;
    }
    for (; u < e; u++) {
        acc += g_per_user[(size_t)u * EMB + t];
    }
    out[(size_t)g * EMB + t] = acc;
}

extern "C" void kernel_launch(void* const* d_in, const int* in_sizes, int n_in,
                              void* d_out, int out_size)
{
    const int*   user_ids   = (const int*)  d_in[0];
    const int*   ugid       = (const int*)  d_in[1];
    const int*   bitem      = (const int*)  d_in[2];
    const float* bcnt       = (const float*)d_in[3];
    const int*   buid       = (const int*)  d_in[4];
    const float* user_table = (const float*)d_in[5];
    const float* item_table = (const float*)d_in[6];

    const int n_users    = in_sizes[0];
    const int n_beh      = in_sizes[2];
    const int num_groups = out_size / EMB;

    float* out = (float*)d_out;

    // Kernel 1: one warp per user, 8 warps per block
    {
        int warps_per_block = 8;
        int threads = warps_per_block * 32;
        int blocks = (n_users + warps_per_block - 1) / warps_per_block;
        per_user_kernel<<<blocks, threads>>>(user_ids, bitem, bcnt, buid,
                                             user_table, item_table,
                                             n_users, n_beh);
    }

    // Kernel 2: one block per group
    {
        group_sum_kernel<<<num_groups, EMB>>>(ugid, out, n_users, num_groups);
    }
}